// round 15
// baseline (speedup 1.0000x reference)
#include <cuda_runtime.h>
#include <math.h>
#include <stdint.h>

#define BB 8
#define NN 4096
#define FF 64
#define OO 64
#define KK 20
#define NPTS (BB*NN)
#define FULLM 0xFFFFFFFFu
#define JCH 128
#define NCHUNK (NN/JCH)
#define ITILE 64
#define DSTRIDE 132

// ---------------- scratch (device globals: no allocation allowed) ----------------
__device__ float  g_xT[NPTS*FF];   // transposed: [b][f][n]
__device__ float  g_sq[NPTS];
__device__ float  g_u[NPTS*OO];
__device__ float  g_v[NPTS*OO];
__device__ int    g_idx[NPTS*KK];
__device__ float  g_hmax[NPTS*OO];
__device__ float  g_hmin[NPTS*OO];
__device__ double g_sum[OO];
__device__ double g_ssq[OO];
__device__ float  g_scale[OO];
__device__ float  g_shift[OO];
__device__ int    g_ctr;

// ---------------- smem layout for k_knn (float offsets into dynamic smem) --------
#define SMF_XSI  0                       // 64f x 64i           = 4096 floats
#define SMF_XSJ  4096                    // 64f x 128j          = 8192 floats
#define SMF_DST  (4096 + 8192)           // 64 x 132            = 8448 floats
#define SMF_SQJ  (SMF_DST + 8448)        // 128 floats
#define SMF_HV   (SMF_SQJ + 128)         // 20 x 256            = 5120 floats
#define SMF_TOT  (SMF_HV + 5120)         // 25984 floats = 103936 B

// packed dual-fp32 FMA (Blackwell f32x2 pipe, PTX-only)
__device__ __forceinline__ void ffma2(unsigned long long &acc,
                                      unsigned long long a,
                                      unsigned long long b) {
    asm("fma.rn.f32x2 %0, %1, %2, %0;" : "+l"(acc) : "l"(a), "l"(b));
}
__device__ __forceinline__ unsigned long long dup2(float v) {
    unsigned long long r;
    asm("mov.b64 %0, {%1, %1};" : "=l"(r) : "f"(v));
    return r;
}
__device__ __forceinline__ void unpack2(unsigned long long p, float &lo, float &hi) {
    asm("mov.b64 {%0, %1}, %2;" : "=f"(lo), "=f"(hi) : "l"(p));
}

// ---------------- no-op spacer so the profiler's fixed window hits k_knn ---------
__global__ void k_nop() {}

// ---------------- transpose x[b][n][f] -> xT[b][f][n] ----------------
__global__ __launch_bounds__(256) void k_tr(const float* __restrict__ x) {
    __shared__ float t[32][33];
    const int b = blockIdx.z, n0 = blockIdx.x * 32, f0 = blockIdx.y * 32;
    const int tx = threadIdx.x, ty = threadIdx.y;
    const float* xb = x + (size_t)b * NN * FF;
    #pragma unroll
    for (int r = 0; r < 4; ++r)
        t[ty + 8*r][tx] = xb[(n0 + ty + 8*r)*FF + f0 + tx];
    __syncthreads();
    float* xT = g_xT + (size_t)b * FF * NN;
    #pragma unroll
    for (int r = 0; r < 4; ++r)
        xT[(f0 + ty + 8*r)*NN + n0 + tx] = t[tx][ty + 8*r];
}

// ---------------- u = x*(W1-W2)^T, v = x*W2^T, norms; block0 zeroes stats --------
__global__ __launch_bounds__(256) void k_uv(const float* __restrict__ x,
                                            const float* __restrict__ W) {
    if (blockIdx.x == 0) {
        if (threadIdx.x < OO) { g_sum[threadIdx.x] = 0.0; g_ssq[threadIdx.x] = 0.0; }
        if (threadIdx.x == 0) g_ctr = 0;
    }
    __shared__ float Wm[FF*OO];
    __shared__ float W2s[FF*OO];
    __shared__ float xbuf[8][FF];

    for (int i = threadIdx.x; i < FF*OO; i += 256) {
        int f = i >> 6, o = i & 63;
        float w1 = W[o*128 + f];
        float w2 = W[o*128 + 64 + f];
        Wm[f*OO + o]  = w1 - w2;
        W2s[f*OO + o] = w2;
    }
    __syncthreads();

    const int lane = threadIdx.x & 31, warp = threadIdx.x >> 5;
    const int p0 = blockIdx.x * 64 + warp * 8;

    for (int pp = 0; pp < 8; ++pp) {
        const int p = p0 + pp;
        const float* xr = x + (size_t)p * FF;
        float x0 = xr[lane], x1 = xr[lane + 32];
        xbuf[warp][lane] = x0; xbuf[warp][lane + 32] = x1;
        __syncwarp();

        float s = x0*x0 + x1*x1;
        #pragma unroll
        for (int o = 16; o; o >>= 1) s += __shfl_xor_sync(FULLM, s, o);
        if (lane == 0) g_sq[p] = s;

        float u0 = 0.f, u1 = 0.f, v0 = 0.f, v1 = 0.f;
        #pragma unroll
        for (int f = 0; f < FF; ++f) {
            float xv = xbuf[warp][f];
            u0 = fmaf(Wm[f*OO + lane],       xv, u0);
            u1 = fmaf(Wm[f*OO + lane + 32],  xv, u1);
            v0 = fmaf(W2s[f*OO + lane],      xv, v0);
            v1 = fmaf(W2s[f*OO + lane + 32], xv, v1);
        }
        g_u[(size_t)p*OO + lane]      = u0;
        g_u[(size_t)p*OO + lane + 32] = u1;
        g_v[(size_t)p*OO + lane]      = v0;
        g_v[(size_t)p*OO + lane + 32] = v1;
        __syncwarp();
    }
}

// ---------------- KNN: R5 mainloop (64i x 128j, f32x2) + per-thread heap select --
// 256 thr = 8 warps; warp owns 8 i-rows in the MMA. Distances -> smem DST;
// selection: 4 threads/row, 32 cols each, 20-slot max-heap (values smem, idx local).
__global__ __launch_bounds__(256, 2) void k_knn() {
    extern __shared__ __align__(16) float smem[];
    float* xsi = smem + SMF_XSI;    // [f][64], swizzle chunk4 = i4 ^ (f&15)
    float* xsj = smem + SMF_XSJ;    // [f][128], swizzle chunk4 = j4 ^ (f&31)
    float* DST = smem + SMF_DST;    // [64][DSTRIDE]
    float* SQJ = smem + SMF_SQJ;
    float* HV  = smem + SMF_HV;     // heap values [s][256]

    const int b  = blockIdx.y;
    const int i0 = blockIdx.x * ITILE;
    const float* xT  = g_xT + (size_t)b * FF * NN;
    const float* sqb = g_sq + b * NN;
    const int tid = threadIdx.x, lane = tid & 31, warp = tid >> 5;

    // stage the i-tile: 1024 float4 chunks, 4/thread, coalesced from xT
    #pragma unroll
    for (int r = 0; r < 4; ++r) {
        int id = tid + 256*r;              // [0,1024)
        int f = id >> 4, i4 = id & 15;     // 64 f x 16 i4
        float4 v = *(const float4*)&xT[f*NN + i0 + 4*i4];
        *(float4*)&xsi[f*64 + 4*(i4 ^ (f & 15))] = v;
    }

    float sqi[8];
    #pragma unroll
    for (int r = 0; r < 8; ++r) sqi[r] = sqb[i0 + 8*warp + r];

    // per-thread heap: values in smem (root cached), indices in local
    int hix[KK];
    #pragma unroll
    for (int s = 0; s < KK; ++s) { HV[s*256 + tid] = INFINITY; hix[s] = 0; }
    float rootv = INFINITY;
    const int selrow = tid >> 2, selq = tid & 3;
    const int ig = i0 + selrow;

    const int fs = tid >> 2, slot = tid & 3;   // staging role

    for (int jc = 0; jc < NCHUNK; ++jc) {
        const int j0 = jc * JCH;

        // ---- stage j-chunk: 8 float4/thread, 2 batches (LDG.128 -> STS.128) ----
        {
            const float* srow = xT + fs*NN + j0;
            #pragma unroll
            for (int bb2 = 0; bb2 < 2; ++bb2) {
                float4 vv[4];
                #pragma unroll
                for (int k = 0; k < 4; ++k) {
                    int j4 = slot + 4*(4*bb2 + k);
                    vv[k] = *(const float4*)&srow[4*j4];
                }
                #pragma unroll
                for (int k = 0; k < 4; ++k) {
                    int j4 = slot + 4*(4*bb2 + k);
                    *(float4*)&xsj[fs*128 + 4*(j4 ^ (fs & 31))] = vv[k];
                }
            }
            if (tid < JCH) SQJ[tid] = sqb[j0 + tid];
        }
        __syncthreads();

        unsigned long long accP[4][4];
        #pragma unroll
        for (int m = 0; m < 4; ++m)
            #pragma unroll
            for (int q = 0; q < 4; ++q) accP[m][q] = 0ull;

        #pragma unroll 16
        for (int f = 0; f < FF; ++f) {
            ulonglong2 aA = *(const ulonglong2*)&xsi[f*64 + 4*((2*warp)     ^ (f & 15))];
            ulonglong2 aB = *(const ulonglong2*)&xsi[f*64 + 4*((2*warp + 1) ^ (f & 15))];
            float4 bv = *(const float4*)&xsj[f*128 + 4*(lane ^ (f & 31))];
            unsigned long long b0 = dup2(bv.x), b1 = dup2(bv.y),
                               b2 = dup2(bv.z), b3 = dup2(bv.w);
            ffma2(accP[0][0], aA.x, b0); ffma2(accP[0][1], aA.x, b1);
            ffma2(accP[0][2], aA.x, b2); ffma2(accP[0][3], aA.x, b3);
            ffma2(accP[1][0], aA.y, b0); ffma2(accP[1][1], aA.y, b1);
            ffma2(accP[1][2], aA.y, b2); ffma2(accP[1][3], aA.y, b3);
            ffma2(accP[2][0], aB.x, b0); ffma2(accP[2][1], aB.x, b1);
            ffma2(accP[2][2], aB.x, b2); ffma2(accP[2][3], aB.x, b3);
            ffma2(accP[3][0], aB.y, b0); ffma2(accP[3][1], aB.y, b1);
            ffma2(accP[3][2], aB.y, b2); ffma2(accP[3][3], aB.y, b3);
        }

        // epilogue: distances -> DST (identical float math to R5)
        float4 sq4 = *(const float4*)&SQJ[4*lane];
        const float sqj[4] = {sq4.x, sq4.y, sq4.z, sq4.w};

        #pragma unroll
        for (int m = 0; m < 4; ++m) {
            float dot[2][4];
            #pragma unroll
            for (int q = 0; q < 4; ++q) unpack2(accP[m][q], dot[0][q], dot[1][q]);
            #pragma unroll
            for (int h = 0; h < 2; ++h) {
                const int r  = 2*m + h;
                const int igr = i0 + 8*warp + r;
                const bool diag = (igr >> 7) == (j0 >> 7);
                float4 d;
                d.x = fmaf(-2.f, dot[h][0], sqi[r] + sqj[0]);
                d.y = fmaf(-2.f, dot[h][1], sqi[r] + sqj[1]);
                d.z = fmaf(-2.f, dot[h][2], sqi[r] + sqj[2]);
                d.w = fmaf(-2.f, dot[h][3], sqi[r] + sqj[3]);
                if (diag) {
                    int jl = igr - j0 - 4*lane;     // lane's cols are 4*lane..+3
                    if (jl == 0) d.x = INFINITY;
                    if (jl == 1) d.y = INFINITY;
                    if (jl == 2) d.z = INFINITY;
                    if (jl == 3) d.w = INFINITY;
                }
                *(float4*)&DST[(8*warp + r)*DSTRIDE + 4*lane] = d;
            }
        }
        __syncthreads();   // DST complete before selection reads

        // ---- selection: 4 threads/row, cols selq+4k, per-thread max-heap ----
        {
            const float* drow = DST + selrow*DSTRIDE;
            #pragma unroll 8
            for (int k = 0; k < 32; ++k) {
                const int col = selq + 4*k;
                float dv = drow[col];
                if (dv < rootv) {
                    const int jg = j0 + col;
                    int s = 0;
                    for (;;) {
                        int c1 = 2*s + 1;
                        if (c1 >= KK) break;
                        int c2 = c1 + 1;
                        float v1 = HV[c1*256 + tid];
                        float v2 = (c2 < KK) ? HV[c2*256 + tid] : -INFINITY;
                        int   big = (v2 > v1) ? c2 : c1;
                        float bvv = fmaxf(v1, v2);
                        if (bvv <= dv) break;
                        HV[s*256 + tid] = bvv;
                        hix[s] = hix[big];
                        s = big;
                    }
                    HV[s*256 + tid] = dv;
                    hix[s] = jg;
                    rootv = HV[tid];
                }
            }
        }
        __syncthreads();   // selection done before next chunk's staging/DST writes
    }

    // ---- merge 4 heaps per row (thread with selq==0 absorbs the other 3) ----
    int* ISC = (int*)(smem + SMF_XSJ);        // reuse xsj as index scratch
    #pragma unroll
    for (int s = 0; s < KK; ++s) ISC[tid*KK + s] = hix[s];
    __syncthreads();
    if (selq == 0) {
        #pragma unroll
        for (int t = 1; t < 4; ++t) {
            #pragma unroll
            for (int s = 0; s < KK; ++s) {
                float v = HV[s*256 + tid + t];
                if (v < rootv) {
                    int ix = ISC[(tid + t)*KK + s];
                    int s2 = 0;
                    for (;;) {
                        int c1 = 2*s2 + 1;
                        if (c1 >= KK) break;
                        int c2 = c1 + 1;
                        float v1 = HV[c1*256 + tid];
                        float v2 = (c2 < KK) ? HV[c2*256 + tid] : -INFINITY;
                        int   big = (v2 > v1) ? c2 : c1;
                        float bvv = fmaxf(v1, v2);
                        if (bvv <= v) break;
                        HV[s2*256 + tid] = bvv;
                        hix[s2] = hix[big];
                        s2 = big;
                    }
                    HV[s2*256 + tid] = v;
                    hix[s2] = ix;
                    rootv = HV[tid];
                }
            }
        }
        #pragma unroll
        for (int s = 0; s < KK; ++s)
            g_idx[(size_t)(b*NN + ig)*KK + s] = hix[s];
    }
}

// ---------------- fuse: h = u_n + v_j, max/min, channel sums; last block -> BN ---
__global__ __launch_bounds__(256) void k_fuse(const float* __restrict__ gamma,
                                              const float* __restrict__ beta) {
    const int tid = threadIdx.x, lane = tid & 31, warp = tid >> 5;
    const int p0 = blockIdx.x * 64 + warp * 8;
    float s0 = 0.f, s1 = 0.f, q0 = 0.f, q1 = 0.f;

    for (int pp = 0; pp < 8; ++pp) {
        const int p = p0 + pp;
        const int vbase = (p >> 12) << 18;
        int myj = 0;
        if (lane < KK) myj = g_idx[(size_t)p*KK + lane];
        float u0 = g_u[(size_t)p*OO + lane];
        float u1 = g_u[(size_t)p*OO + lane + 32];
        float mx0 = -INFINITY, mx1 = -INFINITY, mn0 = INFINITY, mn1 = INFINITY;
        #pragma unroll
        for (int k = 0; k < KK; ++k) {
            int j = __shfl_sync(FULLM, myj, k);
            const float* vp = g_v + vbase + j*OO;
            float v0 = vp[lane], v1 = vp[lane + 32];
            float h0 = u0 + v0, h1 = u1 + v1;
            mx0 = fmaxf(mx0, h0); mn0 = fminf(mn0, h0);
            mx1 = fmaxf(mx1, h1); mn1 = fminf(mn1, h1);
            s0 += h0; q0 = fmaf(h0, h0, q0);
            s1 += h1; q1 = fmaf(h1, h1, q1);
        }
        g_hmax[(size_t)p*OO + lane]      = mx0;
        g_hmax[(size_t)p*OO + lane + 32] = mx1;
        g_hmin[(size_t)p*OO + lane]      = mn0;
        g_hmin[(size_t)p*OO + lane + 32] = mn1;
    }

    __shared__ float sb[8][OO], qb[8][OO];
    sb[warp][lane] = s0; sb[warp][lane + 32] = s1;
    qb[warp][lane] = q0; qb[warp][lane + 32] = q1;
    __syncthreads();
    if (tid < OO) {
        float a = 0.f, c = 0.f;
        #pragma unroll
        for (int w = 0; w < 8; ++w) { a += sb[w][tid]; c += qb[w][tid]; }
        atomicAdd(&g_sum[tid], (double)a);
        atomicAdd(&g_ssq[tid], (double)c);
    }
    __syncthreads();

    __shared__ int amLast;
    if (tid == 0) {
        __threadfence();
        amLast = (atomicAdd(&g_ctr, 1) == (int)gridDim.x - 1);
    }
    __syncthreads();
    if (amLast) {
        __threadfence();
        if (tid < OO) {
            const double cnt = (double)NPTS * (double)KK;
            double m   = g_sum[tid] / cnt;
            double var = g_ssq[tid] / cnt - m * m;
            float a = gamma[tid] * rsqrtf((float)var + 1e-5f);
            g_scale[tid] = a;
            g_shift[tid] = beta[tid] - (float)m * a;
        }
    }
}

// ---------------- apply BN + ReLU to the pooled extrema ----------------
__global__ __launch_bounds__(256) void k_final(float* __restrict__ out) {
    int t = blockIdx.x * 256 + threadIdx.x;
    float4 mx = ((const float4*)g_hmax)[t];
    float4 mn = ((const float4*)g_hmin)[t];
    int o = (t * 4) & 63;
    float a0 = g_scale[o+0], a1 = g_scale[o+1], a2 = g_scale[o+2], a3 = g_scale[o+3];
    float4 r;
    r.x = fmaxf(fmaf(a0, (a0 >= 0.f) ? mx.x : mn.x, g_shift[o+0]), 0.f);
    r.y = fmaxf(fmaf(a1, (a1 >= 0.f) ? mx.y : mn.y, g_shift[o+1]), 0.f);
    r.z = fmaxf(fmaf(a2, (a2 >= 0.f) ? mx.z : mn.z, g_shift[o+2]), 0.f);
    r.w = fmaxf(fmaf(a3, (a3 >= 0.f) ? mx.w : mn.w, g_shift[o+3]), 0.f);
    ((float4*)out)[t] = r;
}

extern "C" void kernel_launch(void* const* d_in, const int* in_sizes, int n_in,
                              void* d_out, int out_size) {
    const float* x     = (const float*)d_in[0];
    const float* W     = (const float*)d_in[1];
    // d_in[2] (conv bias b) cancels exactly under BatchNorm: unused.
    const float* gamma = (const float*)d_in[3];
    const float* beta  = (const float*)d_in[4];
    float* out = (float*)d_out;

    const int knn_smem = SMF_TOT * sizeof(float);   // 103936 B
    cudaFuncSetAttribute(k_knn, cudaFuncAttributeMaxDynamicSharedMemorySize, knn_smem);

    k_tr   <<<dim3(NN/32, FF/32, BB), dim3(32, 8)>>>(x);
    k_uv   <<<NPTS/64, 256>>>(x, W);
    k_nop  <<<1, 32>>>();
    k_knn  <<<dim3(NN/ITILE, BB), 256, knn_smem>>>();   // 4th launch -> profiled
    k_fuse <<<NPTS/64, 256>>>(gamma, beta);
    k_final<<<NPTS*OO/1024, 256>>>(out);
}

// round 16
// speedup vs baseline: 4.2951x; 4.2951x over previous
#include <cuda_runtime.h>
#include <math.h>
#include <stdint.h>

#define BB 8
#define NN 4096
#define FF 64
#define OO 64
#define KK 20
#define NPTS (BB*NN)
#define FULLM 0xFFFFFFFFu
#define JCH 128
#define NCHUNK (NN/JCH)
#define ITILE 64

// ---------------- scratch (device globals: no allocation allowed) ----------------
__device__ float  g_xT[NPTS*FF];   // transposed: [b][f][n]
__device__ float  g_sq[NPTS];
__device__ float  g_u[NPTS*OO];
__device__ float  g_v[NPTS*OO];
__device__ int    g_idx[NPTS*KK];
__device__ float  g_hmax[NPTS*OO];
__device__ float  g_hmin[NPTS*OO];
__device__ double g_sum[OO];
__device__ double g_ssq[OO];
__device__ float  g_scale[OO];
__device__ float  g_shift[OO];
__device__ int    g_ctr;

// packed dual-fp32 FMA (Blackwell f32x2 pipe, PTX-only)
__device__ __forceinline__ void ffma2(unsigned long long &acc,
                                      unsigned long long a,
                                      unsigned long long b) {
    asm("fma.rn.f32x2 %0, %1, %2, %0;" : "+l"(acc) : "l"(a), "l"(b));
}
__device__ __forceinline__ unsigned long long dup2(float v) {
    unsigned long long r;
    asm("mov.b64 %0, {%1, %1};" : "=l"(r) : "f"(v));
    return r;
}
__device__ __forceinline__ void unpack2(unsigned long long p, float &lo, float &hi) {
    asm("mov.b64 {%0, %1}, %2;" : "=f"(lo), "=f"(hi) : "l"(p));
}

// ---------------- no-op spacer so the profiler's fixed window hits k_knn ---------
__global__ void k_nop() {}

// ---------------- transpose x[b][n][f] -> xT[b][f][n] ----------------
__global__ __launch_bounds__(256) void k_tr(const float* __restrict__ x) {
    __shared__ float t[32][33];
    const int b = blockIdx.z, n0 = blockIdx.x * 32, f0 = blockIdx.y * 32;
    const int tx = threadIdx.x, ty = threadIdx.y;
    const float* xb = x + (size_t)b * NN * FF;
    #pragma unroll
    for (int r = 0; r < 4; ++r)
        t[ty + 8*r][tx] = xb[(n0 + ty + 8*r)*FF + f0 + tx];
    __syncthreads();
    float* xT = g_xT + (size_t)b * FF * NN;
    #pragma unroll
    for (int r = 0; r < 4; ++r)
        xT[(f0 + ty + 8*r)*NN + n0 + tx] = t[tx][ty + 8*r];
}

// ---------------- u = x*(W1-W2)^T, v = x*W2^T, norms; block0 zeroes stats --------
__global__ __launch_bounds__(256) void k_uv(const float* __restrict__ x,
                                            const float* __restrict__ W) {
    if (blockIdx.x == 0) {
        if (threadIdx.x < OO) { g_sum[threadIdx.x] = 0.0; g_ssq[threadIdx.x] = 0.0; }
        if (threadIdx.x == 0) g_ctr = 0;
    }
    __shared__ float Wm[FF*OO];
    __shared__ float W2s[FF*OO];
    __shared__ float xbuf[8][FF];

    for (int i = threadIdx.x; i < FF*OO; i += 256) {
        int f = i >> 6, o = i & 63;
        float w1 = W[o*128 + f];
        float w2 = W[o*128 + 64 + f];
        Wm[f*OO + o]  = w1 - w2;
        W2s[f*OO + o] = w2;
    }
    __syncthreads();

    const int lane = threadIdx.x & 31, warp = threadIdx.x >> 5;
    const int p0 = blockIdx.x * 64 + warp * 8;

    for (int pp = 0; pp < 8; ++pp) {
        const int p = p0 + pp;
        const float* xr = x + (size_t)p * FF;
        float x0 = xr[lane], x1 = xr[lane + 32];
        xbuf[warp][lane] = x0; xbuf[warp][lane + 32] = x1;
        __syncwarp();

        float s = x0*x0 + x1*x1;
        #pragma unroll
        for (int o = 16; o; o >>= 1) s += __shfl_xor_sync(FULLM, s, o);
        if (lane == 0) g_sq[p] = s;

        float u0 = 0.f, u1 = 0.f, v0 = 0.f, v1 = 0.f;
        #pragma unroll
        for (int f = 0; f < FF; ++f) {
            float xv = xbuf[warp][f];
            u0 = fmaf(Wm[f*OO + lane],       xv, u0);
            u1 = fmaf(Wm[f*OO + lane + 32],  xv, u1);
            v0 = fmaf(W2s[f*OO + lane],      xv, v0);
            v1 = fmaf(W2s[f*OO + lane + 32], xv, v1);
        }
        g_u[(size_t)p*OO + lane]      = u0;
        g_u[(size_t)p*OO + lane + 32] = u1;
        g_v[(size_t)p*OO + lane]      = v0;
        g_v[(size_t)p*OO + lane + 32] = v1;
        __syncwarp();
    }
}

// ---------------- KNN: R5 structure (64i x 128j, f32x2, double-buffered) ---------
// 256 thr = 8 warps; warp owns 8 i-rows, lane owns 4 j. One barrier per chunk.
// Changes vs R5: coalesced xT staging; all-distances-first + one combined ballot.
__global__ __launch_bounds__(256, 2) void k_knn() {
    extern __shared__ __align__(16) float smem[];
    float* xsi = smem;              // [f][64], swizzle chunk4 = i4 ^ (f&15)
    float* xsj = smem + FF*64;      // two buffers of [f][128], chunk4 = j4 ^ (f&31)

    const int b  = blockIdx.y;
    const int i0 = blockIdx.x * ITILE;
    const float* xT  = g_xT + (size_t)b * FF * NN;
    const float* sqb = g_sq + b * NN;
    const int tid = threadIdx.x, lane = tid & 31, warp = tid >> 5;
    const int fs = tid >> 2, slot = tid & 3;   // staging role: f-row, j4 slot

    // stage the i-tile: 1024 float4 chunks, 4/thread, coalesced from xT
    #pragma unroll
    for (int r = 0; r < 4; ++r) {
        int id = tid + 256*r;              // [0,1024)
        int f = id >> 4, i4 = id & 15;     // 64 f x 16 i4
        float4 v = *(const float4*)&xT[f*NN + i0 + 4*i4];
        *(float4*)&xsi[f*64 + 4*(i4 ^ (f & 15))] = v;
    }

    // stage j-chunk 0 into buffer 0 (coalesced LDG.128 -> swizzled STS.128)
    {
        const float* srow = xT + fs*NN;
        #pragma unroll
        for (int k = 0; k < 8; ++k) {
            int j4 = slot + 4*k;
            float4 v = *(const float4*)&srow[4*j4];
            *(float4*)&xsj[fs*128 + 4*(j4 ^ (fs & 31))] = v;
        }
    }

    float sqi[8];
    #pragma unroll
    for (int r = 0; r < 8; ++r) sqi[r] = sqb[i0 + 8*warp + r];

    // sorted top-20: lanes 0..19 hold ascending (val, idx); curmax = slot-19 value
    float bestv[8], curmax[8];
    int   besti[8];
    #pragma unroll
    for (int r = 0; r < 8; ++r) { bestv[r] = INFINITY; curmax[r] = INFINITY; besti[r] = 0; }

    __syncthreads();

    for (int jc = 0; jc < NCHUNK; ++jc) {
        const int j0 = jc * JCH;
        const float* cur = xsj + (jc & 1) * (FF*128);

        // stage NEXT chunk into the other buffer (overlaps with compute below)
        if (jc + 1 < NCHUNK) {
            float* nxt = xsj + ((jc + 1) & 1) * (FF*128);
            const float* srow = xT + fs*NN + j0 + JCH;
            #pragma unroll
            for (int k = 0; k < 8; ++k) {
                int j4 = slot + 4*k;
                float4 v = *(const float4*)&srow[4*j4];
                *(float4*)&nxt[fs*128 + 4*(j4 ^ (fs & 31))] = v;
            }
        }

        unsigned long long accP[4][4];
        #pragma unroll
        for (int m = 0; m < 4; ++m)
            #pragma unroll
            for (int q = 0; q < 4; ++q) accP[m][q] = 0ull;

        #pragma unroll 16
        for (int f = 0; f < FF; ++f) {
            ulonglong2 aA = *(const ulonglong2*)&xsi[f*64 + 4*((2*warp)     ^ (f & 15))];
            ulonglong2 aB = *(const ulonglong2*)&xsi[f*64 + 4*((2*warp + 1) ^ (f & 15))];
            float4 bv = *(const float4*)&cur[f*128 + 4*(lane ^ (f & 31))];
            unsigned long long b0 = dup2(bv.x), b1 = dup2(bv.y),
                               b2 = dup2(bv.z), b3 = dup2(bv.w);
            ffma2(accP[0][0], aA.x, b0); ffma2(accP[0][1], aA.x, b1);
            ffma2(accP[0][2], aA.x, b2); ffma2(accP[0][3], aA.x, b3);
            ffma2(accP[1][0], aA.y, b0); ffma2(accP[1][1], aA.y, b1);
            ffma2(accP[1][2], aA.y, b2); ffma2(accP[1][3], aA.y, b3);
            ffma2(accP[2][0], aB.x, b0); ffma2(accP[2][1], aB.x, b1);
            ffma2(accP[2][2], aB.x, b2); ffma2(accP[2][3], aB.x, b3);
            ffma2(accP[3][0], aB.y, b0); ffma2(accP[3][1], aB.y, b1);
            ffma2(accP[3][2], aB.y, b2); ffma2(accP[3][3], aB.y, b3);
        }

        float4 sq4 = *(const float4*)&sqb[j0 + 4*lane];
        const float sqj[4] = {sq4.x, sq4.y, sq4.z, sq4.w};

        // ---- compute ALL distances first (reuses accP's registers), row mins ----
        float d[8][4], dmin[8];
        #pragma unroll
        for (int m = 0; m < 4; ++m) {
            float dot[2][4];
            #pragma unroll
            for (int q = 0; q < 4; ++q) unpack2(accP[m][q], dot[0][q], dot[1][q]);
            #pragma unroll
            for (int h = 0; h < 2; ++h) {
                const int r  = 2*m + h;
                const int ig = i0 + 8*warp + r;
                const bool diag = (ig >> 7) == (j0 >> 7);
                #pragma unroll
                for (int q = 0; q < 4; ++q)
                    d[r][q] = fmaf(-2.f, dot[h][q], sqi[r] + sqj[q]);
                if (diag) {
                    #pragma unroll
                    for (int q = 0; q < 4; ++q)
                        if (ig == j0 + 4*lane + q) d[r][q] = INFINITY;
                }
                dmin[r] = fminf(fminf(d[r][0], d[r][1]), fminf(d[r][2], d[r][3]));
            }
        }
        // combined conservative skip: if no lane beats ANY row's threshold, done
        float allmin = dmin[0], cmax = curmax[0];
        #pragma unroll
        for (int r = 1; r < 8; ++r) {
            allmin = fminf(allmin, dmin[r]);
            cmax   = fmaxf(cmax,   curmax[r]);
        }
        if (__ballot_sync(FULLM, allmin < cmax)) {
            #pragma unroll
            for (int r = 0; r < 8; ++r) {
                const int ig = i0 + 8*warp + r;
                if (__ballot_sync(FULLM, dmin[r] < curmax[r])) {
                    #pragma unroll
                    for (int q = 0; q < 4; ++q) {
                        float v = d[r][q];
                        unsigned mmask = __ballot_sync(FULLM, v < curmax[r]);
                        while (mmask) {
                            int src  = __ffs(mmask) - 1;
                            float cv = __shfl_sync(FULLM, v, src);
                            int   cj = j0 + 4*src + q;
                            float upv = __shfl_up_sync(FULLM, bestv[r], 1);
                            int   upi = __shfl_up_sync(FULLM, besti[r], 1);
                            float p18 = __shfl_sync(FULLM, bestv[r], 18);
                            bool shift = (lane < KK) && (bestv[r] > cv);
                            unsigned pm = __ballot_sync(FULLM, shift);
                            int first = __ffs(pm) - 1;
                            if (shift) {
                                bestv[r] = (lane == first) ? cv : upv;
                                besti[r] = (lane == first) ? cj : upi;
                            }
                            curmax[r] = fmaxf(p18, cv);
                            if (lane == src) v = INFINITY;
                            mmask = __ballot_sync(FULLM, v < curmax[r]);
                        }
                    }
                }
            }
        }
        __syncthreads();
    }

    #pragma unroll
    for (int r = 0; r < 8; ++r)
        if (lane < KK)
            g_idx[(size_t)(b*NN + i0 + 8*warp + r)*KK + lane] = besti[r];
}

// ---------------- fuse: h = u_n + v_j, max/min, channel sums; last block -> BN ---
__global__ __launch_bounds__(256) void k_fuse(const float* __restrict__ gamma,
                                              const float* __restrict__ beta) {
    const int tid = threadIdx.x, lane = tid & 31, warp = tid >> 5;
    const int p0 = blockIdx.x * 64 + warp * 8;
    float s0 = 0.f, s1 = 0.f, q0 = 0.f, q1 = 0.f;

    for (int pp = 0; pp < 8; ++pp) {
        const int p = p0 + pp;
        const int vbase = (p >> 12) << 18;
        int myj = 0;
        if (lane < KK) myj = g_idx[(size_t)p*KK + lane];
        float u0 = g_u[(size_t)p*OO + lane];
        float u1 = g_u[(size_t)p*OO + lane + 32];
        float mx0 = -INFINITY, mx1 = -INFINITY, mn0 = INFINITY, mn1 = INFINITY;
        #pragma unroll
        for (int k = 0; k < KK; ++k) {
            int j = __shfl_sync(FULLM, myj, k);
            const float* vp = g_v + vbase + j*OO;
            float v0 = vp[lane], v1 = vp[lane + 32];
            float h0 = u0 + v0, h1 = u1 + v1;
            mx0 = fmaxf(mx0, h0); mn0 = fminf(mn0, h0);
            mx1 = fmaxf(mx1, h1); mn1 = fminf(mn1, h1);
            s0 += h0; q0 = fmaf(h0, h0, q0);
            s1 += h1; q1 = fmaf(h1, h1, q1);
        }
        g_hmax[(size_t)p*OO + lane]      = mx0;
        g_hmax[(size_t)p*OO + lane + 32] = mx1;
        g_hmin[(size_t)p*OO + lane]      = mn0;
        g_hmin[(size_t)p*OO + lane + 32] = mn1;
    }

    __shared__ float sb[8][OO], qb[8][OO];
    sb[warp][lane] = s0; sb[warp][lane + 32] = s1;
    qb[warp][lane] = q0; qb[warp][lane + 32] = q1;
    __syncthreads();
    if (tid < OO) {
        float a = 0.f, c = 0.f;
        #pragma unroll
        for (int w = 0; w < 8; ++w) { a += sb[w][tid]; c += qb[w][tid]; }
        atomicAdd(&g_sum[tid], (double)a);
        atomicAdd(&g_ssq[tid], (double)c);
    }
    __syncthreads();

    __shared__ int amLast;
    if (tid == 0) {
        __threadfence();
        amLast = (atomicAdd(&g_ctr, 1) == (int)gridDim.x - 1);
    }
    __syncthreads();
    if (amLast) {
        __threadfence();
        if (tid < OO) {
            const double cnt = (double)NPTS * (double)KK;
            double m   = g_sum[tid] / cnt;
            double var = g_ssq[tid] / cnt - m * m;
            float a = gamma[tid] * rsqrtf((float)var + 1e-5f);
            g_scale[tid] = a;
            g_shift[tid] = beta[tid] - (float)m * a;
        }
    }
}

// ---------------- apply BN + ReLU to the pooled extrema ----------------
__global__ __launch_bounds__(256) void k_final(float* __restrict__ out) {
    int t = blockIdx.x * 256 + threadIdx.x;
    float4 mx = ((const float4*)g_hmax)[t];
    float4 mn = ((const float4*)g_hmin)[t];
    int o = (t * 4) & 63;
    float a0 = g_scale[o+0], a1 = g_scale[o+1], a2 = g_scale[o+2], a3 = g_scale[o+3];
    float4 r;
    r.x = fmaxf(fmaf(a0, (a0 >= 0.f) ? mx.x : mn.x, g_shift[o+0]), 0.f);
    r.y = fmaxf(fmaf(a1, (a1 >= 0.f) ? mx.y : mn.y, g_shift[o+1]), 0.f);
    r.z = fmaxf(fmaf(a2, (a2 >= 0.f) ? mx.z : mn.z, g_shift[o+2]), 0.f);
    r.w = fmaxf(fmaf(a3, (a3 >= 0.f) ? mx.w : mn.w, g_shift[o+3]), 0.f);
    ((float4*)out)[t] = r;
}

extern "C" void kernel_launch(void* const* d_in, const int* in_sizes, int n_in,
                              void* d_out, int out_size) {
    const float* x     = (const float*)d_in[0];
    const float* W     = (const float*)d_in[1];
    // d_in[2] (conv bias b) cancels exactly under BatchNorm: unused.
    const float* gamma = (const float*)d_in[3];
    const float* beta  = (const float*)d_in[4];
    float* out = (float*)d_out;

    const int knn_smem = (FF*64 + 2*FF*128) * sizeof(float);   // 80 KB
    cudaFuncSetAttribute(k_knn, cudaFuncAttributeMaxDynamicSharedMemorySize, knn_smem);

    k_tr   <<<dim3(NN/32, FF/32, BB), dim3(32, 8)>>>(x);
    k_uv   <<<NPTS/64, 256>>>(x, W);
    k_nop  <<<1, 32>>>();
    k_knn  <<<dim3(NN/ITILE, BB), 256, knn_smem>>>();   // 4th launch -> profiled
    k_fuse <<<NPTS/64, 256>>>(gamma, beta);
    k_final<<<NPTS*OO/1024, 256>>>(out);
}